// round 5
// baseline (speedup 1.0000x reference)
#include <cuda_runtime.h>
#include <stdint.h>
#include <math.h>

#define CC    256
#define HH    256
#define WW    512
#define NPIX  (HH*WW)      // 131072
#define FH    256

// ---------------------------------------------------------------------------
// Device scratch (static — no allocations allowed)
// ---------------------------------------------------------------------------
__device__ float g_aux [(size_t)CC * NPIX];
__device__ float g_Maux[(size_t)CC * NPIX];
__device__ float g_Wb  [2 * 72 * 2048 * 2];   // frag-ordered tf32 weights (2.25MB)
__device__ float g_logitM[NPIX];
__device__ float g_logitA[NPIX];
__device__ float g_mask [NPIX];
__device__ int   g_face [NPIX];
__device__ int   g_off  [NPIX * 4];
__device__ float g_gw   [NPIX * 4];

// ---------------------------------------------------------------------------
// helpers
// ---------------------------------------------------------------------------
__device__ __forceinline__ uint32_t smem_u32(const void* p) {
    uint32_t a;
    asm("{ .reg .u64 t; cvta.to.shared.u64 t, %1; cvt.u32.u64 %0, t; }" : "=r"(a) : "l"(p));
    return a;
}
__device__ __forceinline__ uint32_t cvt_tf32(float f) {
    uint32_t u; asm("cvt.rna.tf32.f32 %0, %1;" : "=r"(u) : "f"(f)); return u;
}
__device__ __forceinline__ void sts32(uint32_t a, uint32_t x) {
    asm volatile("st.shared.b32 [%0], %1;" :: "r"(a), "r"(x) : "memory");
}
__device__ __forceinline__ uint32_t lds32(uint32_t a) {
    uint32_t r; asm volatile("ld.shared.b32 %0, [%1];" : "=r"(r) : "r"(a)); return r;
}
__device__ __forceinline__ void mma_tf32(float* d, const uint32_t* a, const uint32_t* b) {
    asm volatile(
        "mma.sync.aligned.m16n8k8.row.col.f32.tf32.tf32.f32 "
        "{%0,%1,%2,%3}, {%4,%5,%6,%7}, {%8,%9}, {%0,%1,%2,%3};"
        : "+f"(d[0]), "+f"(d[1]), "+f"(d[2]), "+f"(d[3])
        : "r"(a[0]), "r"(a[1]), "r"(a[2]), "r"(a[3]), "r"(b[0]), "r"(b[1]));
}

// ---------------------------------------------------------------------------
// 1) per-pixel cube2equi geometry
// ---------------------------------------------------------------------------
__global__ void geo_kernel() {
    int p = blockIdx.x * blockDim.x + threadIdx.x;
    if (p >= NPIX) return;
    int oy = p / WW, ox = p % WW;
    const float PI = 3.14159265358979323846f;
    float theta = ((ox + 0.5f) / (float)WW) * (2.0f * PI) - PI;
    float phi   = 0.5f * PI - ((oy + 0.5f) / (float)HH) * PI;
    float st = sinf(theta), ct = cosf(theta);
    float sp = sinf(phi),   cp = cosf(phi);
    float dx = cp * st, dy = sp, dz = cp * ct;
    float ax = fabsf(dx), ay = fabsf(dy), az = fabsf(dz);
    float mx = fmaxf(fmaxf(ax, ay), az);
    float px = dx / mx, py = dy / mx, pz = dz / mx;
    bool cz = (az >= ax) && (az >= ay);
    bool cx = (!cz) && (ax >= ay);
    int face = cz ? (dz > 0.f ? 2 : 0) : cx ? (dx > 0.f ? 4 : 3) : (dy > 0.f ? 5 : 1);
    float a  = cz ? (dz > 0.f ? px : -px) : cx ? (dx > 0.f ? -pz : pz) : px;
    float bc = (cz || cx) ? -py : (dy > 0.f ? pz : -pz);
    float uu = fminf(fmaxf((a  + 1.0f) * 0.5f * (float)(FH - 1), 0.0f), (float)(FH - 1));
    float vv = fminf(fmaxf((bc + 1.0f) * 0.5f * (float)(FH - 1), 0.0f), (float)(FH - 1));
    int u0 = (int)floorf(uu), v0 = (int)floorf(vv);
    int u1 = min(u0 + 1, FH - 1), v1 = min(v0 + 1, FH - 1);
    float wu = uu - (float)u0, wv = vv - (float)v0;
    g_face[p] = face;
    g_off[p*4+0] = v0 * FH + u0; g_off[p*4+1] = v0 * FH + u1;
    g_off[p*4+2] = v1 * FH + u0; g_off[p*4+3] = v1 * FH + u1;
    g_gw [p*4+0] = (1.f-wv)*(1.f-wu); g_gw[p*4+1] = (1.f-wv)*wu;
    g_gw [p*4+2] = wv*(1.f-wu);       g_gw[p*4+3] = wv*wu;
}

// ---------------------------------------------------------------------------
// 2) aux = cube2equi(cube)
// ---------------------------------------------------------------------------
__global__ void aux_kernel(const float* __restrict__ fb, const float* __restrict__ fd,
                           const float* __restrict__ fu) {
    int idx = blockIdx.x * blockDim.x + threadIdx.x;
    if (idx >= CC * NPIX) return;
    int p = idx & (NPIX - 1);
    int c = idx >> 17;
    int f = g_face[p];
    const float* base = (f == 0) ? fb : (f == 1) ? fd : (f == 5) ? fu : nullptr;
    float v = 0.0f;
    if (base) {
        const float* bc = base + (size_t)c * (FH * FH);
        v = g_gw[p*4+0]*bc[g_off[p*4+0]] + g_gw[p*4+1]*bc[g_off[p*4+1]]
          + g_gw[p*4+2]*bc[g_off[p*4+2]] + g_gw[p*4+3]*bc[g_off[p*4+3]];
    }
    g_aux[idx] = v;
}

// ---------------------------------------------------------------------------
// 3) weights -> fragment-ordered tf32 (same layout as R4, validated)
//    g_Wb[half][q=72][kstep=4][ntile=16][lane=32][2]
// ---------------------------------------------------------------------------
__global__ void wtb_kernel(const float* __restrict__ Wf) {
    int idx = blockIdx.x * blockDim.x + threadIdx.x;
    if (idx >= 2 * 72 * 2048) return;
    int lane  = idx & 31;
    int ntile = (idx >> 5) & 15;
    int kstep = (idx >> 9) & 3;
    int qq    = idx >> 11;
    int q     = qq % 72;
    int half  = qq / 72;
    int icc = q / 9, tap = q % 9;
    int oc  = half * 128 + ntile * 8 + (lane >> 2);
    int ic0 = icc * 32 + kstep * 8 + (lane & 3);
    float b0 = Wf[(oc * CC + ic0) * 9 + tap];
    float b1 = Wf[(oc * CC + ic0 + 4) * 9 + tap];
    g_Wb[idx * 2 + 0] = __uint_as_float(cvt_tf32(b0));
    g_Wb[idx * 2 + 1] = __uint_as_float(cvt_tf32(b1));
}

// ---------------------------------------------------------------------------
// 4) tf32 mma.sync conv: CTA = 128 px x 256 oc, 8 warps (2M x 4N),
//    warp tile 64px x 64oc (128 accumulators).
//    A: image slab in smem per 32-ic chunk (3 rows x 130 px x 32 ic, pitch 152),
//       fragments via conflict-free LDS.32 (3*152 = 456 == 8 mod 32).
//    B: direct LDG.64 from fragment-ordered g_Wb (L2-resident).
// ---------------------------------------------------------------------------
#define PADX   152
#define AIMGF  (32 * 3 * PADX)          // floats in slab = 14592
#define SM_BIAS (AIMGF * 4)             // 58368
#define SM_WM   (SM_BIAS + 1024)
#define SM_RED  (SM_WM + 1024)
#define SMEM_SZ (SM_RED + 2048)         // 62464

__global__ __launch_bounds__(256, 1)
void conv_mma(const float* __restrict__ in, const float* __restrict__ bias,
              const float* __restrict__ wm, float* __restrict__ outp,
              float* __restrict__ logit)
{
    extern __shared__ char smem[];
    const uint32_t sb = smem_u32(smem);

    const int t    = threadIdx.x;
    const int w    = t >> 5;
    const int lane = t & 31;
    const int mw   = w >> 2;        // 0..1 : pixel half
    const int nw   = w & 3;         // 0..3 : oc quarter (64 oc)

    const int px0 = blockIdx.x * 128;
    const int y   = px0 >> 9;
    const int x0  = px0 & 511;

    if (t < 256) {
        ((float*)(smem + SM_BIAS))[t] = bias[t];
        ((float*)(smem + SM_WM))[t]   = wm[t];
    }

    float acc[4][8][4];
#pragma unroll
    for (int i = 0; i < 4; i++)
#pragma unroll
        for (int j = 0; j < 8; j++)
#pragma unroll
            for (int k = 0; k < 4; k++) acc[i][j][k] = 0.0f;

    // B base (float2 index): half = nw>>1, nti = (nw&1)*8 + j
    const uint32_t b_nwoff = (uint32_t)(nw >> 1) * (72u * 2048u) + (uint32_t)(nw & 1) * 256u + (uint32_t)lane;
    const float2* wb2 = (const float2*)g_Wb;

    // A fragment lane constants
    const int frag_k = lane & 3;                 // k low
    const int frag_m = mw * 64 + (lane >> 2);    // pixel row base

#pragma unroll 1
    for (int icc = 0; icc < 8; icc++) {
        const int ic0 = icc * 32;
        __syncthreads();
        // ---- stage A slab: warp w loads ic = w*4 .. w*4+3 ----
        {
#pragma unroll
            for (int ii = 0; ii < 4; ii++) {
                const int ic = w * 4 + ii;
                const float* gp = in + (size_t)(ic0 + ic) * NPIX;
#pragma unroll
                for (int ry = 0; ry < 3; ry++) {
                    const int gy = y + ry - 1;
                    const bool yok = (gy >= 0) && (gy < HH);
                    const uint32_t rowb = sb + (uint32_t)((ic * 3 + ry) * PADX) * 4u;
                    const float* rp = gp + gy * WW;
#pragma unroll
                    for (int xb = 0; xb < 5; xb++) {
                        const int x = xb * 32 + lane;
                        if (x < 130) {
                            const int gx = x0 + x - 1;
                            float v = (yok && gx >= 0 && gx < WW) ? __ldg(rp + gx) : 0.0f;
                            sts32(rowb + (uint32_t)x * 4u, cvt_tf32(v));
                        }
                    }
                }
            }
        }
        __syncthreads();

        // ---- consume 9 taps ----
#pragma unroll 1
        for (int tap = 0; tap < 9; tap++) {
            const int ky = tap / 3, kx = tap % 3;
            const int q  = icc * 9 + tap;
            const uint32_t bq = (uint32_t)q * 2048u + b_nwoff;
#pragma unroll
            for (int ks = 0; ks < 4; ks++) {
                // A fragments: conflict-free scalar LDS
                const int kk = ks * 8 + frag_k;
                const uint32_t a0 = sb + (uint32_t)(((kk * 3 + ky) * PADX) + kx + frag_m) * 4u;
                uint32_t af[4][4];
#pragma unroll
                for (int mt = 0; mt < 4; mt++) {
                    const uint32_t am = a0 + (uint32_t)(mt * 16) * 4u;
                    af[mt][0] = lds32(am);
                    af[mt][1] = lds32(am + 32u);                 // m+8
                    af[mt][2] = lds32(am + 4u * 3u * PADX * 4u); // k+4
                    af[mt][3] = lds32(am + 4u * 3u * PADX * 4u + 32u);
                }
                // B fragments: prefetch all 8
                uint32_t bf[8][2];
#pragma unroll
                for (int j = 0; j < 8; j++) {
                    float2 v = __ldg(wb2 + bq + (uint32_t)ks * 512u + (uint32_t)j * 32u);
                    bf[j][0] = __float_as_uint(v.x);
                    bf[j][1] = __float_as_uint(v.y);
                }
#pragma unroll
                for (int mt = 0; mt < 4; mt++)
#pragma unroll
                    for (int j = 0; j < 8; j++)
                        mma_tf32(acc[mt][j], af[mt], bf[j]);
            }
        }
    }

    // ---- epilogue: bias+ReLU, optional store, Wm-dot -> full per-pixel logit ----
    const float* sBias = (const float*)(smem + SM_BIAS);
    const float* sWm   = (const float*)(smem + SM_WM);
    float* sRed        = (float*)(smem + SM_RED);

    float lp[4][2];
#pragma unroll
    for (int mt = 0; mt < 4; mt++) { lp[mt][0] = 0.f; lp[mt][1] = 0.f; }

#pragma unroll
    for (int mt = 0; mt < 4; mt++) {
        const int pxa = px0 + mw * 64 + mt * 16 + (lane >> 2);
        const int pxb = pxa + 8;
#pragma unroll
        for (int j = 0; j < 8; j++) {
            const int ocl = (nw * 8 + j) * 8 + 2 * (lane & 3);
            const float b0 = sBias[ocl], b1 = sBias[ocl + 1];
            const float w0 = sWm[ocl],   w1 = sWm[ocl + 1];
            float v00 = fmaxf(acc[mt][j][0] + b0, 0.f);
            float v01 = fmaxf(acc[mt][j][1] + b1, 0.f);
            float v10 = fmaxf(acc[mt][j][2] + b0, 0.f);
            float v11 = fmaxf(acc[mt][j][3] + b1, 0.f);
            if (outp) {
                outp[(size_t)ocl       * NPIX + pxa] = v00;
                outp[(size_t)(ocl + 1) * NPIX + pxa] = v01;
                outp[(size_t)ocl       * NPIX + pxb] = v10;
                outp[(size_t)(ocl + 1) * NPIX + pxb] = v11;
            }
            lp[mt][0] = fmaf(w0, v00, fmaf(w1, v01, lp[mt][0]));
            lp[mt][1] = fmaf(w0, v10, fmaf(w1, v11, lp[mt][1]));
        }
    }
#pragma unroll
    for (int mt = 0; mt < 4; mt++)
#pragma unroll
        for (int r = 0; r < 2; r++) {
            float v = lp[mt][r];
            v += __shfl_xor_sync(0xffffffffu, v, 1);
            v += __shfl_xor_sync(0xffffffffu, v, 2);
            lp[mt][r] = v;
        }
    __syncthreads();
    if ((lane & 3) == 0) {
#pragma unroll
        for (int mt = 0; mt < 4; mt++) {
            const int pxl = mw * 64 + mt * 16 + (lane >> 2);
            sRed[nw * 128 + pxl]     = lp[mt][0];
            sRed[nw * 128 + pxl + 8] = lp[mt][1];
        }
    }
    __syncthreads();
    if (t < 128) {
        float s = sRed[t] + sRed[128 + t] + sRed[256 + t] + sRed[384 + t];
        logit[px0 + t] = s;
    }
}

// ---------------------------------------------------------------------------
// 5) mask = sigmoid(bm + logitM + logitA)
// ---------------------------------------------------------------------------
__global__ void mask_kernel(const float* __restrict__ bm) {
    int p = blockIdx.x * blockDim.x + threadIdx.x;
    if (p >= NPIX) return;
    float s = bm[0] + g_logitM[p] + g_logitA[p];
    g_mask[p] = 1.0f / (1.0f + expf(-s));
}

// ---------------------------------------------------------------------------
// 6) out = m + mask * Maux
// ---------------------------------------------------------------------------
__global__ void final_kernel(const float* __restrict__ m, float* __restrict__ out) {
    int i4 = blockIdx.x * blockDim.x + threadIdx.x;
    if (i4 >= (CC * NPIX) / 4) return;
    int idx = i4 * 4;
    int p   = idx & (NPIX - 1);
    const float4 mv = ((const float4*)m)[i4];
    const float4 av = ((const float4*)g_Maux)[i4];
    const float4 kv = *(const float4*)&g_mask[p];
    float4 o;
    o.x = fmaf(kv.x, av.x, mv.x);
    o.y = fmaf(kv.y, av.y, mv.y);
    o.z = fmaf(kv.z, av.z, mv.z);
    o.w = fmaf(kv.w, av.w, mv.w);
    ((float4*)out)[i4] = o;
}

// ---------------------------------------------------------------------------
// launch
// ---------------------------------------------------------------------------
extern "C" void kernel_launch(void* const* d_in, const int* in_sizes, int n_in,
                              void* d_out, int out_size) {
    const float* m  = (const float*)d_in[0];
    const float* fb = (const float*)d_in[1];
    const float* fu = (const float*)d_in[2];
    const float* fd = (const float*)d_in[3];
    const float* Wf = (const float*)d_in[4];
    const float* bf = (const float*)d_in[5];
    const float* Wm = (const float*)d_in[6];
    const float* bm = (const float*)d_in[7];
    float* out = (float*)d_out;

    float* gAux  = nullptr; cudaGetSymbolAddress((void**)&gAux,  g_aux);
    float* gMaux = nullptr; cudaGetSymbolAddress((void**)&gMaux, g_Maux);
    float* gLM   = nullptr; cudaGetSymbolAddress((void**)&gLM,   g_logitM);
    float* gLA   = nullptr; cudaGetSymbolAddress((void**)&gLA,   g_logitA);

    cudaFuncSetAttribute(conv_mma, cudaFuncAttributeMaxDynamicSharedMemorySize, SMEM_SZ);

    geo_kernel<<<(NPIX + 255) / 256, 256>>>();
    wtb_kernel<<<(2 * 72 * 2048 + 255) / 256, 256>>>(Wf);
    aux_kernel<<<(CC * NPIX + 255) / 256, 256>>>(fb, fd, fu);

    conv_mma<<<NPIX / 128, 256, SMEM_SZ>>>(m,    bf, Wm,       nullptr, gLM);
    conv_mma<<<NPIX / 128, 256, SMEM_SZ>>>(gAux, bf, Wm + CC,  gMaux,   gLA);

    mask_kernel<<<(NPIX + 255) / 256, 256>>>(bm);
    final_kernel<<<((CC * NPIX) / 4 + 255) / 256, 256>>>(m, out);
}

// round 6
// speedup vs baseline: 1.1886x; 1.1886x over previous
#include <cuda_runtime.h>
#include <stdint.h>
#include <math.h>

#define CC    256
#define HH    256
#define WW    512
#define NPIX  (HH*WW)      // 131072
#define FH    256

// ---------------------------------------------------------------------------
// Device scratch (static — no allocations allowed)
// ---------------------------------------------------------------------------
__device__ float g_aux [(size_t)CC * NPIX];
__device__ float g_Maux[(size_t)CC * NPIX];
__device__ float g_Wb  [2 * 72 * 2048 * 2];   // frag-ordered tf32 weights (2.25MB)
__device__ float g_logitM[NPIX];
__device__ float g_logitA[NPIX];
__device__ float g_mask [NPIX];
__device__ int   g_face [NPIX];
__device__ int   g_off  [NPIX * 4];
__device__ float g_gw   [NPIX * 4];

// ---------------------------------------------------------------------------
// helpers
// ---------------------------------------------------------------------------
__device__ __forceinline__ uint32_t smem_u32(const void* p) {
    uint32_t a;
    asm("{ .reg .u64 t; cvta.to.shared.u64 t, %1; cvt.u32.u64 %0, t; }" : "=r"(a) : "l"(p));
    return a;
}
__device__ __forceinline__ uint32_t cvt_tf32(float f) {
    uint32_t u; asm("cvt.rna.tf32.f32 %0, %1;" : "=r"(u) : "f"(f)); return u;
}
__device__ __forceinline__ void sts32(uint32_t a, uint32_t x) {
    asm volatile("st.shared.b32 [%0], %1;" :: "r"(a), "r"(x) : "memory");
}
__device__ __forceinline__ uint32_t lds32(uint32_t a) {
    uint32_t r; asm volatile("ld.shared.b32 %0, [%1];" : "=r"(r) : "r"(a)); return r;
}
__device__ __forceinline__ void mma_tf32(float* d, const uint32_t* a, const uint32_t* b) {
    asm volatile(
        "mma.sync.aligned.m16n8k8.row.col.f32.tf32.tf32.f32 "
        "{%0,%1,%2,%3}, {%4,%5,%6,%7}, {%8,%9}, {%0,%1,%2,%3};"
        : "+f"(d[0]), "+f"(d[1]), "+f"(d[2]), "+f"(d[3])
        : "r"(a[0]), "r"(a[1]), "r"(a[2]), "r"(a[3]), "r"(b[0]), "r"(b[1]));
}

// ---------------------------------------------------------------------------
// 1) per-pixel cube2equi geometry
// ---------------------------------------------------------------------------
__global__ void geo_kernel() {
    int p = blockIdx.x * blockDim.x + threadIdx.x;
    if (p >= NPIX) return;
    int oy = p / WW, ox = p % WW;
    const float PI = 3.14159265358979323846f;
    float theta = ((ox + 0.5f) / (float)WW) * (2.0f * PI) - PI;
    float phi   = 0.5f * PI - ((oy + 0.5f) / (float)HH) * PI;
    float st = sinf(theta), ct = cosf(theta);
    float sp = sinf(phi),   cp = cosf(phi);
    float dx = cp * st, dy = sp, dz = cp * ct;
    float ax = fabsf(dx), ay = fabsf(dy), az = fabsf(dz);
    float mx = fmaxf(fmaxf(ax, ay), az);
    float px = dx / mx, py = dy / mx, pz = dz / mx;
    bool cz = (az >= ax) && (az >= ay);
    bool cx = (!cz) && (ax >= ay);
    int face = cz ? (dz > 0.f ? 2 : 0) : cx ? (dx > 0.f ? 4 : 3) : (dy > 0.f ? 5 : 1);
    float a  = cz ? (dz > 0.f ? px : -px) : cx ? (dx > 0.f ? -pz : pz) : px;
    float bc = (cz || cx) ? -py : (dy > 0.f ? pz : -pz);
    float uu = fminf(fmaxf((a  + 1.0f) * 0.5f * (float)(FH - 1), 0.0f), (float)(FH - 1));
    float vv = fminf(fmaxf((bc + 1.0f) * 0.5f * (float)(FH - 1), 0.0f), (float)(FH - 1));
    int u0 = (int)floorf(uu), v0 = (int)floorf(vv);
    int u1 = min(u0 + 1, FH - 1), v1 = min(v0 + 1, FH - 1);
    float wu = uu - (float)u0, wv = vv - (float)v0;
    g_face[p] = face;
    g_off[p*4+0] = v0 * FH + u0; g_off[p*4+1] = v0 * FH + u1;
    g_off[p*4+2] = v1 * FH + u0; g_off[p*4+3] = v1 * FH + u1;
    g_gw [p*4+0] = (1.f-wv)*(1.f-wu); g_gw[p*4+1] = (1.f-wv)*wu;
    g_gw [p*4+2] = wv*(1.f-wu);       g_gw[p*4+3] = wv*wu;
}

// ---------------------------------------------------------------------------
// 2) aux = cube2equi(cube)
// ---------------------------------------------------------------------------
__global__ void aux_kernel(const float* __restrict__ fb, const float* __restrict__ fd,
                           const float* __restrict__ fu) {
    int idx = blockIdx.x * blockDim.x + threadIdx.x;
    if (idx >= CC * NPIX) return;
    int p = idx & (NPIX - 1);
    int c = idx >> 17;
    int f = g_face[p];
    const float* base = (f == 0) ? fb : (f == 1) ? fd : (f == 5) ? fu : nullptr;
    float v = 0.0f;
    if (base) {
        const float* bc = base + (size_t)c * (FH * FH);
        v = g_gw[p*4+0]*bc[g_off[p*4+0]] + g_gw[p*4+1]*bc[g_off[p*4+1]]
          + g_gw[p*4+2]*bc[g_off[p*4+2]] + g_gw[p*4+3]*bc[g_off[p*4+3]];
    }
    g_aux[idx] = v;
}

// ---------------------------------------------------------------------------
// 3) weights -> fragment-ordered tf32 (layout validated in R4/R5)
//    g_Wb[half][q=72][kstep=4][ntile=16][lane=32][2]
// ---------------------------------------------------------------------------
__global__ void wtb_kernel(const float* __restrict__ Wf) {
    int idx = blockIdx.x * blockDim.x + threadIdx.x;
    if (idx >= 2 * 72 * 2048) return;
    int lane  = idx & 31;
    int ntile = (idx >> 5) & 15;
    int kstep = (idx >> 9) & 3;
    int qq    = idx >> 11;
    int q     = qq % 72;
    int half  = qq / 72;
    int icc = q / 9, tap = q % 9;
    int oc  = half * 128 + ntile * 8 + (lane >> 2);
    int ic0 = icc * 32 + kstep * 8 + (lane & 3);
    float b0 = Wf[(oc * CC + ic0) * 9 + tap];
    float b1 = Wf[(oc * CC + ic0 + 4) * 9 + tap];
    g_Wb[idx * 2 + 0] = __uint_as_float(cvt_tf32(b0));
    g_Wb[idx * 2 + 1] = __uint_as_float(cvt_tf32(b1));
}

// ---------------------------------------------------------------------------
// 4) tf32 mma.sync conv: CTA = 128 px x 256 oc, 512 threads, 16 warps (2M x 8N),
//    warp tile 64px x 32oc (64 accumulators -> ~115 regs, 16 warps/SM).
//    A: smem image slab per 32-ic chunk, conflict-free LDS.32 fragments.
//    B: direct LDG.64 from frag-ordered g_Wb, ping-pong prefetch across ksteps.
// ---------------------------------------------------------------------------
#define PADX   152
#define AIMGF  (32 * 3 * PADX)          // 14592 floats
#define SM_BIAS (AIMGF * 4)             // 58368
#define SM_WM   (SM_BIAS + 1024)
#define SM_RED  (SM_WM + 1024)
#define SMEM_SZ (SM_RED + 8 * 128 * 4)  // 64512

__global__ __launch_bounds__(512, 1)
void conv_mma(const float* __restrict__ in, const float* __restrict__ bias,
              const float* __restrict__ wm, float* __restrict__ outp,
              float* __restrict__ logit)
{
    extern __shared__ char smem[];
    const uint32_t sb = smem_u32(smem);

    const int t    = threadIdx.x;
    const int w    = t >> 5;
    const int lane = t & 31;
    const int mw   = w >> 3;        // 0..1 : pixel half (64 px)
    const int nw   = w & 7;         // 0..7 : oc eighth (32 oc)

    const int px0 = blockIdx.x * 128;
    const int y   = px0 >> 9;
    const int x0  = px0 & 511;

    if (t < 256) {
        ((float*)(smem + SM_BIAS))[t] = bias[t];
        ((float*)(smem + SM_WM))[t]   = wm[t];
    }

    float acc[4][4][4];
#pragma unroll
    for (int i = 0; i < 4; i++)
#pragma unroll
        for (int j = 0; j < 4; j++)
#pragma unroll
            for (int k = 0; k < 4; k++) acc[i][j][k] = 0.0f;

    // B base (float2 index): half = nw>>2, ntile = (nw&3)*4 + j
    const uint32_t b_nwoff = (uint32_t)(nw >> 2) * (72u * 2048u)
                           + (uint32_t)(nw & 3) * 128u + (uint32_t)lane;
    const float2* wb2 = (const float2*)g_Wb;

    const int frag_k = lane & 3;
    const int frag_m = mw * 64 + (lane >> 2);

#pragma unroll 1
    for (int icc = 0; icc < 8; icc++) {
        const int ic0 = icc * 32;
        __syncthreads();
        // ---- stage A slab: warp w loads ic = 2w, 2w+1 ----
        {
#pragma unroll
            for (int ii = 0; ii < 2; ii++) {
                const int ic = w * 2 + ii;
                const float* gp = in + (size_t)(ic0 + ic) * NPIX;
#pragma unroll
                for (int ry = 0; ry < 3; ry++) {
                    const int gy = y + ry - 1;
                    const bool yok = (gy >= 0) && (gy < HH);
                    const uint32_t rowb = sb + (uint32_t)((ic * 3 + ry) * PADX) * 4u;
                    const float* rp = gp + gy * WW;
#pragma unroll
                    for (int xb = 0; xb < 5; xb++) {
                        const int x = xb * 32 + lane;
                        if (x < 130) {
                            const int gx = x0 + x - 1;
                            float v = (yok && gx >= 0 && gx < WW) ? __ldg(rp + gx) : 0.0f;
                            sts32(rowb + (uint32_t)x * 4u, cvt_tf32(v));
                        }
                    }
                }
            }
        }
        __syncthreads();

        // ---- consume 9 taps ----
#pragma unroll 1
        for (int tap = 0; tap < 9; tap++) {
            const int ky = tap / 3, kx = tap % 3;
            const int q  = icc * 9 + tap;
            const uint32_t bq = (uint32_t)q * 2048u + b_nwoff;

            // ping-pong B prefetch across ksteps
            uint32_t bf0[4][2], bf1[4][2];
#pragma unroll
            for (int j = 0; j < 4; j++) {
                float2 v = __ldg(wb2 + bq + (uint32_t)j * 32u);
                bf0[j][0] = __float_as_uint(v.x);
                bf0[j][1] = __float_as_uint(v.y);
            }
#pragma unroll
            for (int ks = 0; ks < 4; ks++) {
                uint32_t (*cur)[2] = (ks & 1) ? bf1 : bf0;
                uint32_t (*nxt)[2] = (ks & 1) ? bf0 : bf1;
                if (ks < 3) {
#pragma unroll
                    for (int j = 0; j < 4; j++) {
                        float2 v = __ldg(wb2 + bq + (uint32_t)(ks + 1) * 512u + (uint32_t)j * 32u);
                        nxt[j][0] = __float_as_uint(v.x);
                        nxt[j][1] = __float_as_uint(v.y);
                    }
                }
                const int kk = ks * 8 + frag_k;
                const uint32_t a0 = sb + (uint32_t)(((kk * 3 + ky) * PADX) + kx + frag_m) * 4u;
#pragma unroll
                for (int mt = 0; mt < 4; mt++) {
                    uint32_t af[4];
                    const uint32_t am = a0 + (uint32_t)(mt * 16) * 4u;
                    af[0] = lds32(am);
                    af[1] = lds32(am + 32u);                 // m+8
                    af[2] = lds32(am + 4u * 3u * PADX * 4u); // k+4
                    af[3] = lds32(am + 4u * 3u * PADX * 4u + 32u);
#pragma unroll
                    for (int j = 0; j < 4; j++)
                        mma_tf32(acc[mt][j], af, cur[j]);
                }
            }
        }
    }

    // ---- epilogue: bias+ReLU, optional store, Wm-dot -> per-pixel logit ----
    const float* sBias = (const float*)(smem + SM_BIAS);
    const float* sWm   = (const float*)(smem + SM_WM);
    float* sRed        = (float*)(smem + SM_RED);

    float lp[4][2];
#pragma unroll
    for (int mt = 0; mt < 4; mt++) { lp[mt][0] = 0.f; lp[mt][1] = 0.f; }

#pragma unroll
    for (int mt = 0; mt < 4; mt++) {
        const int pxa = px0 + mw * 64 + mt * 16 + (lane >> 2);
        const int pxb = pxa + 8;
#pragma unroll
        for (int j = 0; j < 4; j++) {
            const int ocl = nw * 32 + j * 8 + 2 * (lane & 3);
            const float b0 = sBias[ocl], b1 = sBias[ocl + 1];
            const float w0 = sWm[ocl],   w1 = sWm[ocl + 1];
            float v00 = fmaxf(acc[mt][j][0] + b0, 0.f);
            float v01 = fmaxf(acc[mt][j][1] + b1, 0.f);
            float v10 = fmaxf(acc[mt][j][2] + b0, 0.f);
            float v11 = fmaxf(acc[mt][j][3] + b1, 0.f);
            if (outp) {
                outp[(size_t)ocl       * NPIX + pxa] = v00;
                outp[(size_t)(ocl + 1) * NPIX + pxa] = v01;
                outp[(size_t)ocl       * NPIX + pxb] = v10;
                outp[(size_t)(ocl + 1) * NPIX + pxb] = v11;
            }
            lp[mt][0] = fmaf(w0, v00, fmaf(w1, v01, lp[mt][0]));
            lp[mt][1] = fmaf(w0, v10, fmaf(w1, v11, lp[mt][1]));
        }
    }
#pragma unroll
    for (int mt = 0; mt < 4; mt++)
#pragma unroll
        for (int r = 0; r < 2; r++) {
            float v = lp[mt][r];
            v += __shfl_xor_sync(0xffffffffu, v, 1);
            v += __shfl_xor_sync(0xffffffffu, v, 2);
            lp[mt][r] = v;
        }
    if ((lane & 3) == 0) {
#pragma unroll
        for (int mt = 0; mt < 4; mt++) {
            const int pxl = mw * 64 + mt * 16 + (lane >> 2);
            sRed[nw * 128 + pxl]     = lp[mt][0];
            sRed[nw * 128 + pxl + 8] = lp[mt][1];
        }
    }
    __syncthreads();
    if (t < 128) {
        float s = 0.f;
#pragma unroll
        for (int z = 0; z < 8; z++) s += sRed[z * 128 + t];
        logit[px0 + t] = s;
    }
}

// ---------------------------------------------------------------------------
// 5) mask = sigmoid(bm + logitM + logitA)
// ---------------------------------------------------------------------------
__global__ void mask_kernel(const float* __restrict__ bm) {
    int p = blockIdx.x * blockDim.x + threadIdx.x;
    if (p >= NPIX) return;
    float s = bm[0] + g_logitM[p] + g_logitA[p];
    g_mask[p] = 1.0f / (1.0f + expf(-s));
}

// ---------------------------------------------------------------------------
// 6) out = m + mask * Maux
// ---------------------------------------------------------------------------
__global__ void final_kernel(const float* __restrict__ m, float* __restrict__ out) {
    int i4 = blockIdx.x * blockDim.x + threadIdx.x;
    if (i4 >= (CC * NPIX) / 4) return;
    int idx = i4 * 4;
    int p   = idx & (NPIX - 1);
    const float4 mv = ((const float4*)m)[i4];
    const float4 av = ((const float4*)g_Maux)[i4];
    const float4 kv = *(const float4*)&g_mask[p];
    float4 o;
    o.x = fmaf(kv.x, av.x, mv.x);
    o.y = fmaf(kv.y, av.y, mv.y);
    o.z = fmaf(kv.z, av.z, mv.z);
    o.w = fmaf(kv.w, av.w, mv.w);
    ((float4*)out)[i4] = o;
}

// ---------------------------------------------------------------------------
// launch
// ---------------------------------------------------------------------------
extern "C" void kernel_launch(void* const* d_in, const int* in_sizes, int n_in,
                              void* d_out, int out_size) {
    const float* m  = (const float*)d_in[0];
    const float* fb = (const float*)d_in[1];
    const float* fu = (const float*)d_in[2];
    const float* fd = (const float*)d_in[3];
    const float* Wf = (const float*)d_in[4];
    const float* bf = (const float*)d_in[5];
    const float* Wm = (const float*)d_in[6];
    const float* bm = (const float*)d_in[7];
    float* out = (float*)d_out;

    float* gAux  = nullptr; cudaGetSymbolAddress((void**)&gAux,  g_aux);
    float* gMaux = nullptr; cudaGetSymbolAddress((void**)&gMaux, g_Maux);
    float* gLM   = nullptr; cudaGetSymbolAddress((void**)&gLM,   g_logitM);
    float* gLA   = nullptr; cudaGetSymbolAddress((void**)&gLA,   g_logitA);

    cudaFuncSetAttribute(conv_mma, cudaFuncAttributeMaxDynamicSharedMemorySize, SMEM_SZ);

    geo_kernel<<<(NPIX + 255) / 256, 256>>>();
    wtb_kernel<<<(2 * 72 * 2048 + 255) / 256, 256>>>(Wf);
    aux_kernel<<<(CC * NPIX + 255) / 256, 256>>>(fb, fd, fu);

    conv_mma<<<NPIX / 128, 512, SMEM_SZ>>>(m,    bf, Wm,       nullptr, gLM);
    conv_mma<<<NPIX / 128, 512, SMEM_SZ>>>(gAux, bf, Wm + CC,  gMaux,   gLA);

    mask_kernel<<<(NPIX + 255) / 256, 256>>>(bm);
    final_kernel<<<((CC * NPIX) / 4 + 255) / 256, 256>>>(m, out);
}

// round 7
// speedup vs baseline: 2.0715x; 1.7428x over previous
#include <cuda_runtime.h>
#include <stdint.h>
#include <math.h>

#define CC    256
#define HH    256
#define WW    512
#define NPIX  (HH*WW)      // 131072
#define FH    256

// ---------------------------------------------------------------------------
// Device scratch (static — no allocations allowed)
// ---------------------------------------------------------------------------
__device__ float    g_aux [(size_t)CC * NPIX];
__device__ float    g_Maux[(size_t)CC * NPIX];
__device__ uint32_t g_Wb  [2 * 72 * 2 * 16 * 32 * 2];  // bf16x2 frag-ordered (1.18MB)
__device__ float    g_logitM[NPIX];
__device__ float    g_logitA[NPIX];
__device__ float    g_mask [NPIX];
__device__ int      g_face [NPIX];
__device__ int      g_off  [NPIX * 4];
__device__ float    g_gw   [NPIX * 4];

// ---------------------------------------------------------------------------
// helpers
// ---------------------------------------------------------------------------
__device__ __forceinline__ uint32_t smem_u32(const void* p) {
    uint32_t a;
    asm("{ .reg .u64 t; cvta.to.shared.u64 t, %1; cvt.u32.u64 %0, t; }" : "=r"(a) : "l"(p));
    return a;
}
__device__ __forceinline__ uint32_t pack_bf16x2(float hi, float lo) {
    uint32_t u;
    asm("cvt.rn.bf16x2.f32 %0, %1, %2;" : "=r"(u) : "f"(hi), "f"(lo));
    return u;
}
__device__ __forceinline__ void sts32(uint32_t a, uint32_t x) {
    asm volatile("st.shared.b32 [%0], %1;" :: "r"(a), "r"(x) : "memory");
}
__device__ __forceinline__ uint32_t lds32(uint32_t a) {
    uint32_t r; asm volatile("ld.shared.b32 %0, [%1];" : "=r"(r) : "r"(a)); return r;
}
__device__ __forceinline__ void mma_bf16(float* d, const uint32_t* a, const uint32_t* b) {
    asm volatile(
        "mma.sync.aligned.m16n8k16.row.col.f32.bf16.bf16.f32 "
        "{%0,%1,%2,%3}, {%4,%5,%6,%7}, {%8,%9}, {%0,%1,%2,%3};"
        : "+f"(d[0]), "+f"(d[1]), "+f"(d[2]), "+f"(d[3])
        : "r"(a[0]), "r"(a[1]), "r"(a[2]), "r"(a[3]), "r"(b[0]), "r"(b[1]));
}

// ---------------------------------------------------------------------------
// 1) per-pixel cube2equi geometry
// ---------------------------------------------------------------------------
__global__ void geo_kernel() {
    int p = blockIdx.x * blockDim.x + threadIdx.x;
    if (p >= NPIX) return;
    int oy = p / WW, ox = p % WW;
    const float PI = 3.14159265358979323846f;
    float theta = ((ox + 0.5f) / (float)WW) * (2.0f * PI) - PI;
    float phi   = 0.5f * PI - ((oy + 0.5f) / (float)HH) * PI;
    float st = sinf(theta), ct = cosf(theta);
    float sp = sinf(phi),   cp = cosf(phi);
    float dx = cp * st, dy = sp, dz = cp * ct;
    float ax = fabsf(dx), ay = fabsf(dy), az = fabsf(dz);
    float mx = fmaxf(fmaxf(ax, ay), az);
    float px = dx / mx, py = dy / mx, pz = dz / mx;
    bool cz = (az >= ax) && (az >= ay);
    bool cx = (!cz) && (ax >= ay);
    int face = cz ? (dz > 0.f ? 2 : 0) : cx ? (dx > 0.f ? 4 : 3) : (dy > 0.f ? 5 : 1);
    float a  = cz ? (dz > 0.f ? px : -px) : cx ? (dx > 0.f ? -pz : pz) : px;
    float bc = (cz || cx) ? -py : (dy > 0.f ? pz : -pz);
    float uu = fminf(fmaxf((a  + 1.0f) * 0.5f * (float)(FH - 1), 0.0f), (float)(FH - 1));
    float vv = fminf(fmaxf((bc + 1.0f) * 0.5f * (float)(FH - 1), 0.0f), (float)(FH - 1));
    int u0 = (int)floorf(uu), v0 = (int)floorf(vv);
    int u1 = min(u0 + 1, FH - 1), v1 = min(v0 + 1, FH - 1);
    float wu = uu - (float)u0, wv = vv - (float)v0;
    g_face[p] = face;
    g_off[p*4+0] = v0 * FH + u0; g_off[p*4+1] = v0 * FH + u1;
    g_off[p*4+2] = v1 * FH + u0; g_off[p*4+3] = v1 * FH + u1;
    g_gw [p*4+0] = (1.f-wv)*(1.f-wu); g_gw[p*4+1] = (1.f-wv)*wu;
    g_gw [p*4+2] = wv*(1.f-wu);       g_gw[p*4+3] = wv*wu;
}

// ---------------------------------------------------------------------------
// 2) aux = cube2equi(cube)
// ---------------------------------------------------------------------------
__global__ void aux_kernel(const float* __restrict__ fb, const float* __restrict__ fd,
                           const float* __restrict__ fu) {
    int idx = blockIdx.x * blockDim.x + threadIdx.x;
    if (idx >= CC * NPIX) return;
    int p = idx & (NPIX - 1);
    int c = idx >> 17;
    int f = g_face[p];
    const float* base = (f == 0) ? fb : (f == 1) ? fd : (f == 5) ? fu : nullptr;
    float v = 0.0f;
    if (base) {
        const float* bc = base + (size_t)c * (FH * FH);
        v = g_gw[p*4+0]*bc[g_off[p*4+0]] + g_gw[p*4+1]*bc[g_off[p*4+1]]
          + g_gw[p*4+2]*bc[g_off[p*4+2]] + g_gw[p*4+3]*bc[g_off[p*4+3]];
    }
    g_aux[idx] = v;
}

// ---------------------------------------------------------------------------
// 3) weights -> bf16x2 fragment order for m16n8k16:
//    g_Wb[half][q=72][kstep=2][ntile=16][lane=32][2]
//    u0 = pack(w[k+1], w[k]), u1 = pack(w[k+9], w[k+8]);
//    k = kstep*16 + (lane&3)*2, oc = half*128 + ntile*8 + lane>>2
// ---------------------------------------------------------------------------
__global__ void wtb_kernel(const float* __restrict__ Wf) {
    int idx = blockIdx.x * blockDim.x + threadIdx.x;
    if (idx >= 2 * 72 * 2 * 16 * 32) return;
    int lane  = idx & 31;
    int ntile = (idx >> 5) & 15;
    int kstep = (idx >> 9) & 1;
    int qq    = idx >> 10;
    int q     = qq % 72;
    int half  = qq / 72;
    int icc = q / 9, tap = q % 9;
    int oc  = half * 128 + ntile * 8 + (lane >> 2);
    int ic  = icc * 32 + kstep * 16 + (lane & 3) * 2;
    const float* wp = Wf + (size_t)oc * CC * 9 + tap;
    float w0 = wp[(size_t)ic * 9];
    float w1 = wp[(size_t)(ic + 1) * 9];
    float w8 = wp[(size_t)(ic + 8) * 9];
    float w9 = wp[(size_t)(ic + 9) * 9];
    g_Wb[idx * 2 + 0] = pack_bf16x2(w1, w0);
    g_Wb[idx * 2 + 1] = pack_bf16x2(w9, w8);
}

// ---------------------------------------------------------------------------
// 4) bf16 mma.sync conv: CTA = 128 px x 256 oc, 512 threads, 16 warps (2M x 8N),
//    warp tile 64px x 32oc, m16n8k16 (64 accumulators).
//    A: smem slab of bf16x2 ic-pairs (16 pairs x 3 rows x PADX), conflict-free
//       LDS.32 gives a packed fragment register directly.
//    B: direct LDG.64 from bf16x2 frag-ordered g_Wb (L2-resident, 1.18MB).
// ---------------------------------------------------------------------------
#define PADX    152
#define PAIRSTR (3 * PADX)               // 456 u32 ; 456 % 32 == 8 -> conflict-free
#define AIMGU   (16 * PAIRSTR)           // 7296 u32
#define SM_BIAS (AIMGU * 4)              // 29184
#define SM_WM   (SM_BIAS + 1024)
#define SM_RED  (SM_WM + 1024)
#define SMEM_SZ (SM_RED + 8 * 128 * 4)   // 35328

__global__ __launch_bounds__(512, 1)
void conv_mma(const float* __restrict__ in, const float* __restrict__ bias,
              const float* __restrict__ wm, float* __restrict__ outp,
              float* __restrict__ logit)
{
    extern __shared__ char smem[];
    const uint32_t sb = smem_u32(smem);

    const int t    = threadIdx.x;
    const int w    = t >> 5;
    const int lane = t & 31;
    const int mw   = w >> 3;        // 0..1 : pixel half (64 px)
    const int nw   = w & 7;         // 0..7 : oc eighth (32 oc)

    const int px0 = blockIdx.x * 128;
    const int y   = px0 >> 9;
    const int x0  = px0 & 511;

    if (t < 256) {
        ((float*)(smem + SM_BIAS))[t] = bias[t];
        ((float*)(smem + SM_WM))[t]   = wm[t];
    }

    float acc[4][4][4];
#pragma unroll
    for (int i = 0; i < 4; i++)
#pragma unroll
        for (int j = 0; j < 4; j++)
#pragma unroll
            for (int k = 0; k < 4; k++) acc[i][j][k] = 0.0f;

    // B base (uint2 units): [half][q][kstep][ntile][lane]
    const uint32_t b_nwoff = (uint32_t)(nw >> 2) * (72u * 1024u)
                           + (uint32_t)(nw & 3) * 128u + (uint32_t)lane;
    const uint2* wb2 = (const uint2*)g_Wb;

    const int frag_p = lane & 3;                 // ic-pair low index
    const int frag_m = mw * 64 + (lane >> 2);    // pixel row base

#pragma unroll 1
    for (int icc = 0; icc < 8; icc++) {
        const int ic0 = icc * 32;
        __syncthreads();
        // ---- stage A slab: warp w packs ic pair (2w, 2w+1) ----
        {
            const float* gp0 = in + (size_t)(ic0 + 2 * w) * NPIX;
            const float* gp1 = gp0 + NPIX;
#pragma unroll
            for (int ry = 0; ry < 3; ry++) {
                const int gy = y + ry - 1;
                const bool yok = (gy >= 0) && (gy < HH);
                const uint32_t rowb = sb + (uint32_t)((w * 3 + ry) * PADX) * 4u;
                const long long roff = (long long)gy * WW;
#pragma unroll
                for (int xb = 0; xb < 5; xb++) {
                    const int x = xb * 32 + lane;
                    if (x < 130) {
                        const int gx = x0 + x - 1;
                        const bool ok = yok && gx >= 0 && gx < WW;
                        float v0 = ok ? __ldg(gp0 + roff + gx) : 0.0f;
                        float v1 = ok ? __ldg(gp1 + roff + gx) : 0.0f;
                        sts32(rowb + (uint32_t)x * 4u, pack_bf16x2(v1, v0));
                    }
                }
            }
        }
        __syncthreads();

        // ---- consume 9 taps, 2 k16-steps each ----
#pragma unroll 1
        for (int tap = 0; tap < 9; tap++) {
            const int ky = tap / 3, kx = tap % 3;
            const uint32_t bq = (uint32_t)(icc * 9 + tap) * 1024u + b_nwoff;

            // prefetch both ksteps' B fragments (8 x uint2)
            uint2 bf[2][4];
#pragma unroll
            for (int ks = 0; ks < 2; ks++)
#pragma unroll
                for (int j = 0; j < 4; j++)
                    bf[ks][j] = __ldg(wb2 + bq + (uint32_t)ks * 512u + (uint32_t)j * 32u);

#pragma unroll
            for (int ks = 0; ks < 2; ks++) {
                const int p0 = ks * 8 + frag_p;
                const uint32_t a0 = sb + (uint32_t)((p0 * 3 + ky) * PADX + kx + frag_m) * 4u;
#pragma unroll
                for (int mt = 0; mt < 4; mt++) {
                    uint32_t af[4];
                    const uint32_t am = a0 + (uint32_t)(mt * 16) * 4u;
                    af[0] = lds32(am);                           // (m,     k..k+1)
                    af[1] = lds32(am + 32u);                     // (m+8,   k..k+1)
                    af[2] = lds32(am + 4u * PAIRSTR * 4u);       // (m,   k+8..k+9)
                    af[3] = lds32(am + 4u * PAIRSTR * 4u + 32u); // (m+8, k+8..k+9)
#pragma unroll
                    for (int j = 0; j < 4; j++) {
                        uint32_t bb[2] = { bf[ks][j].x, bf[ks][j].y };
                        mma_bf16(acc[mt][j], af, bb);
                    }
                }
            }
        }
    }

    // ---- epilogue: bias+ReLU, optional store, Wm-dot -> per-pixel logit ----
    const float* sBias = (const float*)(smem + SM_BIAS);
    const float* sWm   = (const float*)(smem + SM_WM);
    float* sRed        = (float*)(smem + SM_RED);

    float lp[4][2];
#pragma unroll
    for (int mt = 0; mt < 4; mt++) { lp[mt][0] = 0.f; lp[mt][1] = 0.f; }

#pragma unroll
    for (int mt = 0; mt < 4; mt++) {
        const int pxa = px0 + mw * 64 + mt * 16 + (lane >> 2);
        const int pxb = pxa + 8;
#pragma unroll
        for (int j = 0; j < 4; j++) {
            const int ocl = nw * 32 + j * 8 + 2 * (lane & 3);
            const float b0 = sBias[ocl], b1 = sBias[ocl + 1];
            const float w0 = sWm[ocl],   w1 = sWm[ocl + 1];
            float v00 = fmaxf(acc[mt][j][0] + b0, 0.f);
            float v01 = fmaxf(acc[mt][j][1] + b1, 0.f);
            float v10 = fmaxf(acc[mt][j][2] + b0, 0.f);
            float v11 = fmaxf(acc[mt][j][3] + b1, 0.f);
            if (outp) {
                outp[(size_t)ocl       * NPIX + pxa] = v00;
                outp[(size_t)(ocl + 1) * NPIX + pxa] = v01;
                outp[(size_t)ocl       * NPIX + pxb] = v10;
                outp[(size_t)(ocl + 1) * NPIX + pxb] = v11;
            }
            lp[mt][0] = fmaf(w0, v00, fmaf(w1, v01, lp[mt][0]));
            lp[mt][1] = fmaf(w0, v10, fmaf(w1, v11, lp[mt][1]));
        }
    }
#pragma unroll
    for (int mt = 0; mt < 4; mt++)
#pragma unroll
        for (int r = 0; r < 2; r++) {
            float v = lp[mt][r];
            v += __shfl_xor_sync(0xffffffffu, v, 1);
            v += __shfl_xor_sync(0xffffffffu, v, 2);
            lp[mt][r] = v;
        }
    if ((lane & 3) == 0) {
#pragma unroll
        for (int mt = 0; mt < 4; mt++) {
            const int pxl = mw * 64 + mt * 16 + (lane >> 2);
            sRed[nw * 128 + pxl]     = lp[mt][0];
            sRed[nw * 128 + pxl + 8] = lp[mt][1];
        }
    }
    __syncthreads();
    if (t < 128) {
        float s = 0.f;
#pragma unroll
        for (int z = 0; z < 8; z++) s += sRed[z * 128 + t];
        logit[px0 + t] = s;
    }
}

// ---------------------------------------------------------------------------
// 5) mask = sigmoid(bm + logitM + logitA)
// ---------------------------------------------------------------------------
__global__ void mask_kernel(const float* __restrict__ bm) {
    int p = blockIdx.x * blockDim.x + threadIdx.x;
    if (p >= NPIX) return;
    float s = bm[0] + g_logitM[p] + g_logitA[p];
    g_mask[p] = 1.0f / (1.0f + expf(-s));
}

// ---------------------------------------------------------------------------
// 6) out = m + mask * Maux
// ---------------------------------------------------------------------------
__global__ void final_kernel(const float* __restrict__ m, float* __restrict__ out) {
    int i4 = blockIdx.x * blockDim.x + threadIdx.x;
    if (i4 >= (CC * NPIX) / 4) return;
    int idx = i4 * 4;
    int p   = idx & (NPIX - 1);
    const float4 mv = ((const float4*)m)[i4];
    const float4 av = ((const float4*)g_Maux)[i4];
    const float4 kv = *(const float4*)&g_mask[p];
    float4 o;
    o.x = fmaf(kv.x, av.x, mv.x);
    o.y = fmaf(kv.y, av.y, mv.y);
    o.z = fmaf(kv.z, av.z, mv.z);
    o.w = fmaf(kv.w, av.w, mv.w);
    ((float4*)out)[i4] = o;
}

// ---------------------------------------------------------------------------
// launch
// ---------------------------------------------------------------------------
extern "C" void kernel_launch(void* const* d_in, const int* in_sizes, int n_in,
                              void* d_out, int out_size) {
    const float* m  = (const float*)d_in[0];
    const float* fb = (const float*)d_in[1];
    const float* fu = (const float*)d_in[2];
    const float* fd = (const float*)d_in[3];
    const float* Wf = (const float*)d_in[4];
    const float* bf = (const float*)d_in[5];
    const float* Wm = (const float*)d_in[6];
    const float* bm = (const float*)d_in[7];
    float* out = (float*)d_out;

    float* gAux  = nullptr; cudaGetSymbolAddress((void**)&gAux,  g_aux);
    float* gMaux = nullptr; cudaGetSymbolAddress((void**)&gMaux, g_Maux);
    float* gLM   = nullptr; cudaGetSymbolAddress((void**)&gLM,   g_logitM);
    float* gLA   = nullptr; cudaGetSymbolAddress((void**)&gLA,   g_logitA);

    cudaFuncSetAttribute(conv_mma, cudaFuncAttributeMaxDynamicSharedMemorySize, SMEM_SZ);

    geo_kernel<<<(NPIX + 255) / 256, 256>>>();
    wtb_kernel<<<(2 * 72 * 2 * 16 * 32 + 255) / 256, 256>>>(Wf);
    aux_kernel<<<(CC * NPIX + 255) / 256, 256>>>(fb, fd, fu);

    conv_mma<<<NPIX / 128, 512, SMEM_SZ>>>(m,    bf, Wm,       nullptr, gLM);
    conv_mma<<<NPIX / 128, 512, SMEM_SZ>>>(gAux, bf, Wm + CC,  gMaux,   gLA);

    mask_kernel<<<(NPIX + 255) / 256, 256>>>(bm);
    final_kernel<<<((CC * NPIX) / 4 + 255) / 256, 256>>>(m, out);
}